// round 5
// baseline (speedup 1.0000x reference)
#include <cuda_runtime.h>

// x1:   (16, 1, 224, 224) fp32
// W:    (288, 1, 3, 3)    fp32
// bias: (1, 288, 222, 222) fp32
// out:  (16, 288, 222, 222) fp32 = relu(conv_valid(x1, W) + bias)

#define B_      16
#define COUT_   288
#define CSPLIT  3
#define CPER    (COUT_ / CSPLIT)    // 96 channels per CTA
#define HIN_    224
#define WIN_    224
#define HOUT_   222
#define WOUT_   222
#define PLANE_  (HOUT_ * WOUT_)     // 49284
#define ROWS_CTA 6                  // rows per CTA (two 3-row halves)
#define IROWS   (ROWS_CTA + 2)      // 8 input rows

__global__ __launch_bounds__(224, 6) void conv_bias_relu_kernel(
    const float* __restrict__ x,
    const float* __restrict__ Wt,
    const float* __restrict__ bias,
    float* __restrict__ out)
{
    __shared__ __align__(16) float sW[CPER * 12];        // 4608 B (9->12 padded)
    __shared__ __align__(8)  float sIn[IROWS][WIN_];     // 7168 B

    const int hg = blockIdx.x;            // 0..36
    const int b  = blockIdx.y;            // 0..15
    const int cg = blockIdx.z;            // 0..2
    const int t  = threadIdx.x;           // 0..223
    const int h0 = hg * ROWS_CTA;
    const int c0 = cg * CPER;

    // Weights: this CTA's 96 channels, padded to 12 floats/channel.
    const float* wsrc = Wt + c0 * 9;
    for (int i = t; i < CPER * 9; i += 224) {
        int c = i / 9, j = i - c * 9;
        sW[c * 12 + j] = wsrc[i];
    }

    // Input: 8 rows x 224 cols; each thread loads one column.
    const float* xb = x + (long)b * HIN_ * WIN_;
    #pragma unroll
    for (int r = 0; r < IROWS; r++) sIn[r][t] = xb[(h0 + r) * WIN_ + t];

    __syncthreads();

    const int half = t / 112;             // 0: rows 0-2, 1: rows 3-5
    const int u    = t - half * 112;      // pixel-pair index 0..110 (111 idle)
    if (u >= 111) return;

    // Taps as packed float2: 5 rows x 2 float2 (cols 2u..2u+3).
    float2 tl[5], tr[5];
    #pragma unroll
    for (int r = 0; r < 5; r++) {
        tl[r] = *reinterpret_cast<const float2*>(&sIn[half * 3 + r][2 * u]);
        tr[r] = *reinterpret_cast<const float2*>(&sIn[half * 3 + r][2 * u + 2]);
    }

    const long ofs = (long)c0 * PLANE_ + (long)(h0 + half * 3) * WOUT_ + 2 * u;
    const float* bp = bias + ofs;
    float*       op = out + (long)b * COUT_ * PLANE_ + ofs;

    // Bias double-buffer: 3 float2 per channel.
    float2 bnx[3];
    #pragma unroll
    for (int r = 0; r < 3; r++) bnx[r] = __ldg((const float2*)(bp + r * WOUT_));

    #pragma unroll 2
    for (int c = 0; c < CPER; c++) {
        const float4 wA = *reinterpret_cast<const float4*>(&sW[c * 12]);     // w0..w3
        const float4 wB = *reinterpret_cast<const float4*>(&sW[c * 12 + 4]); // w4..w7
        const float  w8 = sW[c * 12 + 8];

        float2 bcur[3];
        #pragma unroll
        for (int r = 0; r < 3; r++) bcur[r] = bnx[r];
        if (c + 1 < CPER) {
            bp += PLANE_;
            #pragma unroll
            for (int r = 0; r < 3; r++) bnx[r] = __ldg((const float2*)(bp + r * WOUT_));
        }

        #pragma unroll
        for (int r = 0; r < 3; r++) {
            // pixel 0 taps per row: tl.x, tl.y, tr.x ; pixel 1: tl.y, tr.x, tr.y
            float y0, y1;
            y0 = tl[r].x * wA.x;                 y1 = tl[r].y * wA.x;
            y0 = fmaf(tl[r].y, wA.y, y0);        y1 = fmaf(tr[r].x, wA.y, y1);
            y0 = fmaf(tr[r].x, wA.z, y0);        y1 = fmaf(tr[r].y, wA.z, y1);
            y0 = fmaf(tl[r+1].x, wA.w, y0);      y1 = fmaf(tl[r+1].y, wA.w, y1);
            y0 = fmaf(tl[r+1].y, wB.x, y0);      y1 = fmaf(tr[r+1].x, wB.x, y1);
            y0 = fmaf(tr[r+1].x, wB.y, y0);      y1 = fmaf(tr[r+1].y, wB.y, y1);
            y0 = fmaf(tl[r+2].x, wB.z, y0);      y1 = fmaf(tl[r+2].y, wB.z, y1);
            y0 = fmaf(tl[r+2].y, wB.w, y0);      y1 = fmaf(tr[r+2].x, wB.w, y1);
            y0 = fmaf(tr[r+2].x, w8,  y0);       y1 = fmaf(tr[r+2].y, w8,  y1);
            float2 o;
            o.x = fmaxf(y0 + bcur[r].x, 0.0f);
            o.y = fmaxf(y1 + bcur[r].y, 0.0f);
            __stcs((float2*)(op + r * WOUT_), o);   // streaming store, evict-first
        }
        op += PLANE_;
    }
}

extern "C" void kernel_launch(void* const* d_in, const int* in_sizes, int n_in,
                              void* d_out, int out_size)
{
    const float* x    = (const float*)d_in[0];
    const float* Wt   = (const float*)d_in[1];
    const float* bias = (const float*)d_in[2];
    float*       out  = (float*)d_out;

    dim3 grid(HOUT_ / ROWS_CTA, B_, CSPLIT);   // 37 x 16 x 3 = 1776 CTAs
    dim3 block(224);
    conv_bias_relu_kernel<<<grid, block>>>(x, Wt, bias, out);
}

// round 6
// speedup vs baseline: 1.3681x; 1.3681x over previous
#include <cuda_runtime.h>

// x1:   (16, 1, 224, 224) fp32
// W:    (288, 1, 3, 3)    fp32
// bias: (1, 288, 222, 222) fp32
// out:  (16, 288, 222, 222) fp32 = relu(conv_valid(x1, W) + bias)

#define B_      16
#define COUT_   288
#define HIN_    224
#define WIN_    224
#define HOUT_   222
#define WOUT_   222
#define PLANE_  (HOUT_ * WOUT_)   // 49284
#define RPB     6                 // output rows per CTA (222 = 37*6)
#define IROWS   (RPB + 2)         // 8 input rows

__global__ __launch_bounds__(224, 4) void conv_bias_relu_kernel(
    const float* __restrict__ x,
    const float* __restrict__ Wt,
    const float* __restrict__ bias,
    float* __restrict__ out)
{
    // Weights padded to 12 floats/channel: 2x LDS.128 + 1x LDS.32 per channel.
    __shared__ __align__(16) float sW[COUT_ * 12];   // 13824 B
    __shared__ float sIn[IROWS][WIN_];               //  7168 B

    const int hg = blockIdx.x;           // 0..36  (row group)
    const int b  = blockIdx.y;           // 0..15
    const int t  = threadIdx.x;          // 0..223
    const int h0 = hg * RPB;

    // Cooperative weight load with 9->12 padding.
    for (int i = t; i < COUT_ * 9; i += 224) {
        int c = i / 9, j = i - c * 9;
        sW[c * 12 + j] = Wt[i];
    }

    // Cooperative load of the 8 input rows this CTA needs (each thread = 1 col).
    const float* xb = x + (long)b * HIN_ * WIN_;
    #pragma unroll
    for (int r = 0; r < IROWS; r++) sIn[r][t] = xb[(h0 + r) * WIN_ + t];

    __syncthreads();

    if (t >= WOUT_) return;

    // 24 taps in registers: rows h0..h0+7, cols t..t+2. Invariant over channels.
    float tap[IROWS][3];
    #pragma unroll
    for (int r = 0; r < IROWS; r++) {
        tap[r][0] = sIn[r][t];
        tap[r][1] = sIn[r][t + 1];
        tap[r][2] = sIn[r][t + 2];
    }

    const long ofs = (long)h0 * WOUT_ + t;
    const float* bp = bias + ofs;
    float*       op = out + (long)b * COUT_ * PLANE_ + ofs;

    // Software pipeline: bias for channel c is loaded one full channel ahead,
    // giving each LDG ~an entire channel iteration (x7 warps) of latency cover.
    float bnx[RPB];
    #pragma unroll
    for (int r = 0; r < RPB; r++) bnx[r] = __ldg(bp + r * WOUT_);

    #pragma unroll 2
    for (int c = 0; c < COUT_; c++) {
        const float4 wA = *reinterpret_cast<const float4*>(&sW[c * 12]);     // w0..w3
        const float4 wB = *reinterpret_cast<const float4*>(&sW[c * 12 + 4]); // w4..w7
        const float  w8 = sW[c * 12 + 8];

        float bcur[RPB];
        #pragma unroll
        for (int r = 0; r < RPB; r++) bcur[r] = bnx[r];

        if (c + 1 < COUT_) {
            bp += PLANE_;
            #pragma unroll
            for (int r = 0; r < RPB; r++) bnx[r] = __ldg(bp + r * WOUT_);
        }

        #pragma unroll
        for (int r = 0; r < RPB; r++) {
            float y = tap[r][0] * wA.x;
            y = fmaf(tap[r    ][1], wA.y, y);
            y = fmaf(tap[r    ][2], wA.z, y);
            y = fmaf(tap[r + 1][0], wA.w, y);
            y = fmaf(tap[r + 1][1], wB.x, y);
            y = fmaf(tap[r + 1][2], wB.y, y);
            y = fmaf(tap[r + 2][0], wB.z, y);
            y = fmaf(tap[r + 2][1], wB.w, y);
            y = fmaf(tap[r + 2][2], w8,  y);
            y += bcur[r];
            op[r * WOUT_] = fmaxf(y, 0.0f);
        }
        op += PLANE_;
    }
}

extern "C" void kernel_launch(void* const* d_in, const int* in_sizes, int n_in,
                              void* d_out, int out_size)
{
    const float* x    = (const float*)d_in[0];
    const float* Wt   = (const float*)d_in[1];
    const float* bias = (const float*)d_in[2];
    float*       out  = (float*)d_out;

    dim3 grid(HOUT_ / RPB, B_);   // 37 x 16 = 592 CTAs
    dim3 block(224);              // 7 warps
    conv_bias_relu_kernel<<<grid, block>>>(x, Wt, bias, out);
}